// round 3
// baseline (speedup 1.0000x reference)
#include <cuda_runtime.h>
#include <cuda_bf16.h>
#include <math.h>
#include <stdint.h>

#define Nn 100000
#define Ee 1600000
#define Dd 128
#define Ll 3
#define CAPB 96
#define MAX_OV 8192
#define NDTOT (Nn * Dd)

// ---------------- device scratch (no allocations allowed) ----------------
static __device__ float A_buf[NDTOT];                 // lin1(y) per node
static __device__ float H_buf[NDTOT];                 // running h accumulator
static __device__ int   cnt_buf[Nn];                  // in-degree (int)
static __device__ int   bucket_buf[Nn * CAPB];        // buckets of src ids
static __device__ int   ov_src[MAX_OV];
static __device__ int   ov_dst[MAX_OV];
static __device__ int   ov_cnt;
static __device__ int   g_is64;
static __device__ double g_sum, g_sumsq;

__device__ __forceinline__ uint32_t s2u(const void* p) {
    return (uint32_t)__cvta_generic_to_shared(p);
}

// ---------------- init: zero counters + detect edge dtype ----------------
__global__ void init_kernel(const int* __restrict__ ei) {
    int i = blockIdx.x * blockDim.x + threadIdx.x;
    if (i < Nn) cnt_buf[i] = 0;
    if (i == 0) {
        ov_cnt = 0;
        int all0 = 1;
        for (int k = 0; k < 128; k++) {
            if (ei[2 * k + 1] != 0) { all0 = 0; break; }
        }
        g_is64 = all0;
    }
}

__device__ __forceinline__ int fetch_idx(const int* __restrict__ ei, int pos, int is64) {
    return is64 ? ei[2 * pos] : ei[pos];
}

// ---------------- build bucketed adjacency -------------------------------
__global__ void build_csr(const int* __restrict__ ei) {
    int e = blockIdx.x * blockDim.x + threadIdx.x;
    if (e >= Ee) return;
    int is64 = g_is64;
    int src = fetch_idx(ei, e, is64);
    int dst = fetch_idx(ei, Ee + e, is64);
    int pos = atomicAdd(&cnt_buf[dst], 1);
    if (pos < CAPB) {
        bucket_buf[(size_t)dst * CAPB + pos] = src;
    } else {
        int o = atomicAdd(&ov_cnt, 1);
        if (o < MAX_OV) { ov_src[o] = src; ov_dst[o] = dst; }
    }
}

// ======================= HMMA (mma.sync) helpers ==========================
__device__ __forceinline__ void mma_bf16(float* d, const uint32_t* a, const uint32_t* b) {
    asm volatile("mma.sync.aligned.m16n8k16.row.col.f32.bf16.bf16.f32 "
        "{%0,%1,%2,%3}, {%4,%5,%6,%7}, {%8,%9}, {%0,%1,%2,%3};"
        : "+f"(d[0]), "+f"(d[1]), "+f"(d[2]), "+f"(d[3])
        : "r"(a[0]), "r"(a[1]), "r"(a[2]), "r"(a[3]), "r"(b[0]), "r"(b[1]));
}
__device__ __forceinline__ void ldsm4(uint32_t* r, uint32_t addr) {
    asm volatile("ldmatrix.sync.aligned.m8n8.x4.shared.b16 {%0,%1,%2,%3}, [%4];"
        : "=r"(r[0]), "=r"(r[1]), "=r"(r[2]), "=r"(r[3]) : "r"(addr));
}
__device__ __forceinline__ void ldsm2(uint32_t* r, uint32_t addr) {
    asm volatile("ldmatrix.sync.aligned.m8n8.x2.shared.b16 {%0,%1}, [%2];"
        : "=r"(r[0]), "=r"(r[1]) : "r"(addr));
}

// SMEM tiles: 128 rows x 128 bf16, padded row stride 272B (conflict-free ldmatrix)
#define TSTRIDE 272u
#define TILE_BYTES (128u * TSTRIDE)      // 34816
#define YH_OFF 0u
#define YL_OFF TILE_BYTES
#define WH_OFF (2u * TILE_BYTES)
#define WL_OFF (3u * TILE_BYTES)
#define G_SMEM (4u * TILE_BYTES)         // 139264

// ========= fused GEMM: A_buf = Y@W1+b1 ; H_buf = Y@W3+b3 - deg*(Y@W2) =====
__global__ void __launch_bounds__(256) gemm_fused(const float* __restrict__ Y,
                                                  const float* __restrict__ W1,
                                                  const float* __restrict__ b1,
                                                  const float* __restrict__ W2,
                                                  const float* __restrict__ W3,
                                                  const float* __restrict__ b3) {
    extern __shared__ char smem[];
    uint32_t sb = s2u(smem);
    int tid = threadIdx.x, lane = tid & 31, wid = tid >> 5;
    int warp_m = wid & 3, warp_n = wid >> 2;   // 4 x 2 warps
    int base = blockIdx.x * 128;

    // ---- load Y tile, split fp32 -> bf16 hi/lo ----
    for (int idx = tid; idx < 128 * 64; idx += 256) {
        int r = idx >> 6;
        int k2 = (idx & 63) << 1;
        int row = base + r;
        float2 v = (row < Nn)
            ? *reinterpret_cast<const float2*>(Y + (size_t)row * 128 + k2)
            : make_float2(0.f, 0.f);
        __nv_bfloat16 hx = __float2bfloat16(v.x);
        __nv_bfloat16 hy = __float2bfloat16(v.y);
        __nv_bfloat16 lx = __float2bfloat16(v.x - __bfloat162float(hx));
        __nv_bfloat16 ly = __float2bfloat16(v.y - __bfloat162float(hy));
        uint32_t o = (uint32_t)r * TSTRIDE + (uint32_t)k2 * 2u;
        *reinterpret_cast<__nv_bfloat162*>(smem + YH_OFF + o) = __halves2bfloat162(hx, hy);
        *reinterpret_cast<__nv_bfloat162*>(smem + YL_OFF + o) = __halves2bfloat162(lx, ly);
    }

    const float* Ws[3] = {W2, W3, W1};   // order: W2 (-deg), W3 (+=), W1 (A)

    // per-thread ldmatrix address components
    uint32_t a_row = (uint32_t)(lane & 15);
    uint32_t a_hi  = (uint32_t)(lane >> 4) * 16u;
    uint32_t b_row = (uint32_t)(lane & 7);
    uint32_t b_hi  = (uint32_t)((lane >> 3) & 1) * 16u;

    int m_lane = lane >> 2;                 // row within 8-row group
    int nbase = warp_n * 64 + (lane & 3) * 2;

    for (int w = 0; w < 3; w++) {
        __syncthreads();   // prior ldmatrix reads done before W tiles overwritten
        const float* W = Ws[w];
        // load weight transposed: WT[n][k] = W[k*128+n], split hi/lo
        for (int idx = tid; idx < 128 * 128; idx += 256) {
            int k = idx >> 7, n = idx & 127;
            float v = __ldg(W + idx);
            __nv_bfloat16 h = __float2bfloat16(v);
            __nv_bfloat16 l = __float2bfloat16(v - __bfloat162float(h));
            uint32_t o = (uint32_t)n * TSTRIDE + (uint32_t)k * 2u;
            *reinterpret_cast<__nv_bfloat16*>(smem + WH_OFF + o) = h;
            *reinterpret_cast<__nv_bfloat16*>(smem + WL_OFF + o) = l;
        }
        __syncthreads();

        float acc[2][8][4];
#pragma unroll
        for (int mi = 0; mi < 2; mi++)
#pragma unroll
            for (int ni = 0; ni < 8; ni++)
#pragma unroll
                for (int j = 0; j < 4; j++) acc[mi][ni][j] = 0.f;

#pragma unroll
        for (int k0 = 0; k0 < 8; k0++) {
            uint32_t kb = (uint32_t)k0 * 32u;
            uint32_t ah[2][4], al[2][4];
#pragma unroll
            for (int mi = 0; mi < 2; mi++) {
                uint32_t rowa = (uint32_t)(warp_m * 32 + mi * 16) + a_row;
                uint32_t off = rowa * TSTRIDE + kb + a_hi;
                ldsm4(ah[mi], sb + YH_OFF + off);
                ldsm4(al[mi], sb + YL_OFF + off);
            }
#pragma unroll
            for (int ni = 0; ni < 8; ni++) {
                uint32_t rown = (uint32_t)(warp_n * 64 + ni * 8) + b_row;
                uint32_t off = rown * TSTRIDE + kb + b_hi;
                uint32_t bh[2], bl[2];
                ldsm2(bh, sb + WH_OFF + off);
                ldsm2(bl, sb + WL_OFF + off);
                mma_bf16(acc[0][ni], ah[0], bh);
                mma_bf16(acc[1][ni], ah[1], bh);
                mma_bf16(acc[0][ni], ah[0], bl);
                mma_bf16(acc[1][ni], ah[1], bl);
                mma_bf16(acc[0][ni], al[0], bh);
                mma_bf16(acc[1][ni], al[1], bh);
            }
        }

        // ---- epilogue ----
#pragma unroll
        for (int mi = 0; mi < 2; mi++) {
            int r0 = base + warp_m * 32 + mi * 16 + m_lane;   // and r0+8
#pragma unroll
            for (int half = 0; half < 2; half++) {
                int row = r0 + half * 8;
                if (row >= Nn) continue;
                if (w == 0) {
                    float dg = (float)cnt_buf[row];
#pragma unroll
                    for (int ni = 0; ni < 8; ni++) {
                        int n = nbase + ni * 8;
                        float2 o;
                        o.x = -dg * acc[mi][ni][half * 2 + 0];
                        o.y = -dg * acc[mi][ni][half * 2 + 1];
                        *reinterpret_cast<float2*>(H_buf + (size_t)row * 128 + n) = o;
                    }
                } else if (w == 1) {
#pragma unroll
                    for (int ni = 0; ni < 8; ni++) {
                        int n = nbase + ni * 8;
                        float2 bb = *reinterpret_cast<const float2*>(b3 + n);
                        float2* p = reinterpret_cast<float2*>(H_buf + (size_t)row * 128 + n);
                        float2 cur = *p;
                        cur.x += acc[mi][ni][half * 2 + 0] + bb.x;
                        cur.y += acc[mi][ni][half * 2 + 1] + bb.y;
                        *p = cur;
                    }
                } else {
#pragma unroll
                    for (int ni = 0; ni < 8; ni++) {
                        int n = nbase + ni * 8;
                        float2 bb = *reinterpret_cast<const float2*>(b1 + n);
                        float2 o;
                        o.x = acc[mi][ni][half * 2 + 0] + bb.x;
                        o.y = acc[mi][ni][half * 2 + 1] + bb.y;
                        *reinterpret_cast<float2*>(A_buf + (size_t)row * 128 + n) = o;
                    }
                }
            }
        }
    }
}

// ---------------- gather: H[v] += sum_{j->v} A[j]  (warp per node) --------
__global__ void gather_kernel() {
    if (blockIdx.x == 0 && threadIdx.x == 0) { g_sum = 0.0; g_sumsq = 0.0; }
    int gw = (blockIdx.x * blockDim.x + threadIdx.x) >> 5;
    int lane = threadIdx.x & 31;
    if (gw >= Nn) return;
    int c = cnt_buf[gw];
    if (c > CAPB) c = CAPB;
    const int* bk = bucket_buf + (size_t)gw * CAPB;
    float4 acc = make_float4(0.f, 0.f, 0.f, 0.f);
    int e = 0;
    for (; e + 1 < c; e += 2) {
        int s0 = bk[e], s1 = bk[e + 1];
        float4 a0 = __ldg(reinterpret_cast<const float4*>(A_buf + (size_t)s0 * 128) + lane);
        float4 a1 = __ldg(reinterpret_cast<const float4*>(A_buf + (size_t)s1 * 128) + lane);
        acc.x += a0.x + a1.x; acc.y += a0.y + a1.y;
        acc.z += a0.z + a1.z; acc.w += a0.w + a1.w;
    }
    if (e < c) {
        int s0 = bk[e];
        float4 a0 = __ldg(reinterpret_cast<const float4*>(A_buf + (size_t)s0 * 128) + lane);
        acc.x += a0.x; acc.y += a0.y; acc.z += a0.z; acc.w += a0.w;
    }
    float4* hp = reinterpret_cast<float4*>(H_buf + (size_t)gw * 128) + lane;
    float4 h = *hp;
    h.x += acc.x; h.y += acc.y; h.z += acc.z; h.w += acc.w;
    *hp = h;
}

// ---------------- overflow edges (expected count: 0) ----------------------
__global__ void overflow_fix() {
    int m = ov_cnt;
    if (m > MAX_OV) m = MAX_OV;
    int lane = threadIdx.x & 31;
    int w = threadIdx.x >> 5;
    for (int e = w; e < m; e += 8) {
        int src = ov_src[e], dst = ov_dst[e];
        const float* ap = A_buf + (size_t)src * 128;
        float* hp = H_buf + (size_t)dst * 128;
        for (int k = lane; k < 128; k += 32) atomicAdd(&hp[k], ap[k]);
    }
}

// ---------------- global mean / sumsq (double accumulation) ---------------
__global__ void reduce_stats() {
    int idx = blockIdx.x * blockDim.x + threadIdx.x;
    int stride = gridDim.x * blockDim.x;
    double s = 0.0, ss = 0.0;
    const float4* h4 = reinterpret_cast<const float4*>(H_buf);
    for (int i = idx; i < NDTOT / 4; i += stride) {
        float4 v = h4[i];
        s  += (double)v.x + (double)v.y + (double)v.z + (double)v.w;
        ss += (double)v.x * v.x + (double)v.y * v.y +
              (double)v.z * v.z + (double)v.w * v.w;
    }
#pragma unroll
    for (int o = 16; o > 0; o >>= 1) {
        s  += __shfl_down_sync(0xffffffffu, s, o);
        ss += __shfl_down_sync(0xffffffffu, ss, o);
    }
    __shared__ double sh[2][8];
    int lane = threadIdx.x & 31, w = threadIdx.x >> 5;
    if (lane == 0) { sh[0][w] = s; sh[1][w] = ss; }
    __syncthreads();
    if (threadIdx.x == 0) {
        double ts = 0.0, tss = 0.0;
        for (int i = 0; i < (int)(blockDim.x >> 5); i++) { ts += sh[0][i]; tss += sh[1][i]; }
        atomicAdd(&g_sum, ts);
        atomicAdd(&g_sumsq, tss);
    }
}

// --------- normalize + affine + leaky_relu + residual update --------------
__global__ void final_update(const float* __restrict__ lw, const float* __restrict__ lb,
                             const float* __restrict__ yin, float* __restrict__ yout) {
    double M = (double)NDTOT;
    double mean = g_sum / M;
    double var = g_sumsq / M - mean * mean;
    if (var < 0.0) var = 0.0;
    float inv = 1.0f / ((float)sqrt(var) + 1e-5f);
    float mf = (float)mean;

    int idx = blockIdx.x * blockDim.x + threadIdx.x;
    int stride = gridDim.x * blockDim.x;
    const float4* h4 = reinterpret_cast<const float4*>(H_buf);
    const float4* y4 = reinterpret_cast<const float4*>(yin);
    float4* o4 = reinterpret_cast<float4*>(yout);
    for (int i = idx; i < NDTOT / 4; i += stride) {
        int d = (i * 4) & 127;
        float4 w = *reinterpret_cast<const float4*>(lw + d);
        float4 b = *reinterpret_cast<const float4*>(lb + d);
        float4 h = h4[i];
        float4 y = y4[i];
        float t;
        float4 o;
        t = (h.x - mf) * inv; t = t * w.x + b.x; t = (t >= 0.f) ? t : 0.01f * t; o.x = y.x + t;
        t = (h.y - mf) * inv; t = t * w.y + b.y; t = (t >= 0.f) ? t : 0.01f * t; o.y = y.y + t;
        t = (h.z - mf) * inv; t = t * w.z + b.z; t = (t >= 0.f) ? t : 0.01f * t; o.z = y.z + t;
        t = (h.w - mf) * inv; t = t * w.w + b.w; t = (t >= 0.f) ? t : 0.01f * t; o.w = y.w + t;
        o4[i] = o;
    }
}

// ---------------------------------------------------------------------------
extern "C" void kernel_launch(void* const* d_in, const int* in_sizes, int n_in,
                              void* d_out, int out_size) {
    const float* y0 = (const float*)d_in[0];
    const int*   ei = (const int*)d_in[1];
    const float* W1 = (const float*)d_in[2];
    const float* b1 = (const float*)d_in[3];
    const float* W2 = (const float*)d_in[4];
    const float* W3 = (const float*)d_in[5];
    const float* b3 = (const float*)d_in[6];
    const float* lw = (const float*)d_in[7];
    const float* lb = (const float*)d_in[8];
    float* yout = (float*)d_out;

    (void)in_sizes; (void)n_in; (void)out_size;

    cudaFuncSetAttribute(gemm_fused, cudaFuncAttributeMaxDynamicSharedMemorySize, G_SMEM);

    init_kernel<<<(Nn + 255) / 256, 256>>>(ei);
    build_csr<<<(Ee + 255) / 256, 256>>>(ei);

    const int gemm_blocks = (Nn + 127) / 128;   // 782
    for (int l = 0; l < Ll; l++) {
        const float* yin = (l == 0) ? y0 : yout;
        gemm_fused<<<gemm_blocks, 256, G_SMEM>>>(yin,
                                                 W1 + (size_t)l * Dd * Dd, b1 + (size_t)l * Dd,
                                                 W2 + (size_t)l * Dd * Dd,
                                                 W3 + (size_t)l * Dd * Dd, b3 + (size_t)l * Dd);
        gather_kernel<<<(Nn * 32 + 255) / 256, 256>>>();
        overflow_fix<<<1, 256>>>();
        reduce_stats<<<1024, 256>>>();
        final_update<<<1024, 256>>>(lw + (size_t)l * Dd, lb + (size_t)l * Dd, yin, yout);
    }
}

// round 4
// speedup vs baseline: 1.7636x; 1.7636x over previous
#include <cuda_runtime.h>
#include <cuda_bf16.h>
#include <math.h>
#include <stdint.h>

#define Nn 100000
#define Ee 1600000
#define Dd 128
#define Ll 3
#define CAPB 96
#define MAX_OV 8192
#define NDTOT (Nn * Dd)

// ---------------- device scratch (no allocations allowed) ----------------
static __device__ float A_buf[NDTOT];                  // lin1(y) per node
static __device__ float H_buf[NDTOT];                  // running h accumulator
static __device__ int   cnt_buf[Nn];                   // in-degree
static __device__ int   bucket_buf[Nn * CAPB];         // buckets of src ids
static __device__ int   ov_src[MAX_OV];
static __device__ int   ov_dst[MAX_OV];
static __device__ int   ov_cnt;
static __device__ int   g_is64;
static __device__ double g_sum, g_sumsq;
static __device__ __nv_bfloat16 Yh_buf[NDTOT];         // Y split hi
static __device__ __nv_bfloat16 Yl_buf[NDTOT];         // Y split lo
// Wsp[(l*3+w)*2+h][n][k] bf16 ; w order: 0=W2, 1=W3, 2=W1 ; h: 0=hi,1=lo
static __device__ __nv_bfloat16 Wsp_buf[Ll * 3 * 2 * 128 * 128];

__device__ __forceinline__ uint32_t s2u(const void* p) {
    return (uint32_t)__cvta_generic_to_shared(p);
}

// ---------------- init: zero counters + detect edge dtype ----------------
__global__ void init_kernel(const int* __restrict__ ei) {
    int i = blockIdx.x * blockDim.x + threadIdx.x;
    if (i < Nn) cnt_buf[i] = 0;
    if (i == 0) {
        ov_cnt = 0;
        int all0 = 1;
        for (int k = 0; k < 128; k++) {
            if (ei[2 * k + 1] != 0) { all0 = 0; break; }
        }
        g_is64 = all0;
    }
}

__device__ __forceinline__ int fetch_idx(const int* __restrict__ ei, int pos, int is64) {
    return is64 ? ei[2 * pos] : ei[pos];
}

__global__ void build_csr(const int* __restrict__ ei) {
    int e = blockIdx.x * blockDim.x + threadIdx.x;
    if (e >= Ee) return;
    int is64 = g_is64;
    int src = fetch_idx(ei, e, is64);
    int dst = fetch_idx(ei, Ee + e, is64);
    int pos = atomicAdd(&cnt_buf[dst], 1);
    if (pos < CAPB) {
        bucket_buf[(size_t)dst * CAPB + pos] = src;
    } else {
        int o = atomicAdd(&ov_cnt, 1);
        if (o < MAX_OV) { ov_src[o] = src; ov_dst[o] = dst; }
    }
}

// -------- one-time: split all weights to bf16 hi/lo, transposed [n][k] ----
__global__ void split_weights(const float* __restrict__ W1,
                              const float* __restrict__ W2,
                              const float* __restrict__ W3) {
    int idx = blockIdx.x * blockDim.x + threadIdx.x;   // over Ll*3*16384
    if (idx >= Ll * 3 * 16384) return;
    int lw = idx >> 14;
    int rem = idx & 16383;
    int k = rem >> 7, n = rem & 127;
    int l = lw / 3, w = lw % 3;
    const float* W = (w == 0) ? W2 : (w == 1) ? W3 : W1;
    float v = W[(size_t)l * 16384 + rem];               // W[l][k][n]
    __nv_bfloat16 h = __float2bfloat16(v);
    __nv_bfloat16 lo = __float2bfloat16(v - __bfloat162float(h));
    size_t base = (size_t)(lw * 2) * 16384;
    Wsp_buf[base + (size_t)n * 128 + k] = h;
    Wsp_buf[base + 16384 + (size_t)n * 128 + k] = lo;
}

// -------- split fp32 Y into bf16 hi/lo (layer 0 only) ---------------------
__global__ void split_y(const float* __restrict__ Y) {
    int i = blockIdx.x * blockDim.x + threadIdx.x;     // over NDTOT/2
    if (i >= NDTOT / 2) return;
    float2 v = *reinterpret_cast<const float2*>(Y + 2 * i);
    __nv_bfloat16 hx = __float2bfloat16(v.x);
    __nv_bfloat16 hy = __float2bfloat16(v.y);
    __nv_bfloat16 lx = __float2bfloat16(v.x - __bfloat162float(hx));
    __nv_bfloat16 ly = __float2bfloat16(v.y - __bfloat162float(hy));
    *reinterpret_cast<__nv_bfloat162*>(Yh_buf + 2 * i) = __halves2bfloat162(hx, hy);
    *reinterpret_cast<__nv_bfloat162*>(Yl_buf + 2 * i) = __halves2bfloat162(lx, ly);
}

// ======================= HMMA (mma.sync) helpers ==========================
__device__ __forceinline__ void mma_bf16(float* d, const uint32_t* a, const uint32_t* b) {
    asm volatile("mma.sync.aligned.m16n8k16.row.col.f32.bf16.bf16.f32 "
        "{%0,%1,%2,%3}, {%4,%5,%6,%7}, {%8,%9}, {%0,%1,%2,%3};"
        : "+f"(d[0]), "+f"(d[1]), "+f"(d[2]), "+f"(d[3])
        : "r"(a[0]), "r"(a[1]), "r"(a[2]), "r"(a[3]), "r"(b[0]), "r"(b[1]));
}
__device__ __forceinline__ void ldsm4(uint32_t* r, uint32_t addr) {
    asm volatile("ldmatrix.sync.aligned.m8n8.x4.shared.b16 {%0,%1,%2,%3}, [%4];"
        : "=r"(r[0]), "=r"(r[1]), "=r"(r[2]), "=r"(r[3]) : "r"(addr));
}
__device__ __forceinline__ void cpa16(uint32_t dst, const void* src, int srcsz) {
    asm volatile("cp.async.cg.shared.global [%0], [%1], 16, %2;"
                 :: "r"(dst), "l"(src), "r"(srcsz) : "memory");
}
#define CPA_COMMIT() asm volatile("cp.async.commit_group;" ::: "memory")
#define CPA_WAIT(n)  asm volatile("cp.async.wait_group %0;" :: "n"(n) : "memory")

// SMEM: padded row stride 272B (17x16B), conflict-free ldmatrix
#define TSTRIDE 272u
#define TILE_BYTES (128u * TSTRIDE)      // 34816
#define YH_OFF 0u
#define YL_OFF TILE_BYTES
#define WB(buf, h) ((2u + (uint32_t)(buf) * 2u + (uint32_t)(h)) * TILE_BYTES)
#define G_SMEM (6u * TILE_BYTES)         // 208896

// cp.async one 128x128 bf16 tile (256B rows) into padded smem
__device__ __forceinline__ void copy_w_tile(uint32_t sb, uint32_t off,
                                            const __nv_bfloat16* __restrict__ g, int tid) {
    for (int i = tid; i < 2048; i += 256) {
        int n = i >> 4, c = i & 15;
        cpa16(sb + off + (uint32_t)n * TSTRIDE + (uint32_t)c * 16u,
              g + (size_t)n * 128 + c * 8, 16);
    }
}

// ========= fused GEMM: A = Y@W1+b1 ; H = Y@W3+b3 - deg*(Y@W2) =============
__global__ void __launch_bounds__(256) gemm_fused(int layer,
                                                  const float* __restrict__ b1,
                                                  const float* __restrict__ b3) {
    extern __shared__ char smem[];
    uint32_t sb = s2u(smem);
    int tid = threadIdx.x, lane = tid & 31, wid = tid >> 5;
    int warp_m = wid & 3, warp_n = wid >> 2;   // 4 x 2 warps
    int base = blockIdx.x * 128;

    const __nv_bfloat16* wbase = Wsp_buf + (size_t)(layer * 3) * 2 * 16384;

    // ---- issue Y tiles + W0 (group 0) ----
    for (int t = 0; t < 2; t++) {
        const __nv_bfloat16* src = t ? Yl_buf : Yh_buf;
        uint32_t off = t ? YL_OFF : YH_OFF;
        for (int i = tid; i < 2048; i += 256) {
            int n = i >> 4, c = i & 15;
            int row = base + n;
            int ok = (row < Nn);
            cpa16(sb + off + (uint32_t)n * TSTRIDE + (uint32_t)c * 16u,
                  src + (ok ? ((size_t)row * 128 + c * 8) : 0), ok ? 16 : 0);
        }
    }
    copy_w_tile(sb, WB(0, 0), wbase + 0 * 16384, tid);
    copy_w_tile(sb, WB(0, 1), wbase + 1 * 16384, tid);
    CPA_COMMIT();
    // ---- W1 (group 1) ----
    copy_w_tile(sb, WB(1, 0), wbase + 2 * 16384, tid);
    copy_w_tile(sb, WB(1, 1), wbase + 3 * 16384, tid);
    CPA_COMMIT();

    // per-thread ldmatrix address components
    uint32_t a_row = (uint32_t)(lane & 15);
    uint32_t a_hi  = (uint32_t)(lane >> 4) * 16u;
    uint32_t b_row = (uint32_t)((lane & 7) + ((lane >> 4) << 3));
    uint32_t b_hi  = (uint32_t)((lane >> 3) & 1) * 16u;
    int m_lane = lane >> 2;
    int nbase = warp_n * 64 + (lane & 3) * 2;

    CPA_WAIT(1);          // Y + W0 resident
    __syncthreads();

    for (int w = 0; w < 3; w++) {
        int buf = (w == 1) ? 1 : 0;
        uint32_t whoff = WB(buf, 0), wloff = WB(buf, 1);

        float acc[2][8][4];
#pragma unroll
        for (int mi = 0; mi < 2; mi++)
#pragma unroll
            for (int ni = 0; ni < 8; ni++)
#pragma unroll
                for (int j = 0; j < 4; j++) acc[mi][ni][j] = 0.f;

#pragma unroll
        for (int k0 = 0; k0 < 8; k0++) {
            uint32_t kb = (uint32_t)k0 * 32u;
            uint32_t ah[2][4], al[2][4];
#pragma unroll
            for (int mi = 0; mi < 2; mi++) {
                uint32_t rowa = (uint32_t)(warp_m * 32 + mi * 16) + a_row;
                uint32_t off = rowa * TSTRIDE + kb + a_hi;
                ldsm4(ah[mi], sb + YH_OFF + off);
                ldsm4(al[mi], sb + YL_OFF + off);
            }
#pragma unroll
            for (int bg = 0; bg < 4; bg++) {
                uint32_t rown = (uint32_t)(warp_n * 64 + bg * 16) + b_row;
                uint32_t off = rown * TSTRIDE + kb + b_hi;
                uint32_t bh[4], bl[4];
                ldsm4(bh, sb + whoff + off);
                ldsm4(bl, sb + wloff + off);
#pragma unroll
                for (int sub = 0; sub < 2; sub++) {
                    int ni = bg * 2 + sub;
                    mma_bf16(acc[0][ni], ah[0], bh + 2 * sub);
                    mma_bf16(acc[1][ni], ah[1], bh + 2 * sub);
                    mma_bf16(acc[0][ni], ah[0], bl + 2 * sub);
                    mma_bf16(acc[1][ni], ah[1], bl + 2 * sub);
                    mma_bf16(acc[0][ni], al[0], bh + 2 * sub);
                    mma_bf16(acc[1][ni], al[1], bh + 2 * sub);
                }
            }
        }

        // ---- prefetch / wait management ----
        __syncthreads();                       // all reads of buf done
        if (w == 0) {
            copy_w_tile(sb, WB(0, 0), wbase + 4 * 16384, tid);   // W2 -> buf0
            copy_w_tile(sb, WB(0, 1), wbase + 5 * 16384, tid);
            CPA_COMMIT();
            CPA_WAIT(1);                       // W1 resident
            __syncthreads();
        } else if (w == 1) {
            CPA_WAIT(0);                       // W2 resident
            __syncthreads();
        }

        // ---- epilogue ----
#pragma unroll
        for (int mi = 0; mi < 2; mi++) {
            int r0 = base + warp_m * 32 + mi * 16 + m_lane;
#pragma unroll
            for (int half = 0; half < 2; half++) {
                int row = r0 + half * 8;
                if (row >= Nn) continue;
                if (w == 0) {
                    float dg = (float)cnt_buf[row];
#pragma unroll
                    for (int ni = 0; ni < 8; ni++) {
                        int n = nbase + ni * 8;
                        float2 o;
                        o.x = -dg * acc[mi][ni][half * 2 + 0];
                        o.y = -dg * acc[mi][ni][half * 2 + 1];
                        *reinterpret_cast<float2*>(H_buf + (size_t)row * 128 + n) = o;
                    }
                } else if (w == 1) {
#pragma unroll
                    for (int ni = 0; ni < 8; ni++) {
                        int n = nbase + ni * 8;
                        float2 bb = *reinterpret_cast<const float2*>(b3 + n);
                        float2* p = reinterpret_cast<float2*>(H_buf + (size_t)row * 128 + n);
                        float2 cur = *p;
                        cur.x += acc[mi][ni][half * 2 + 0] + bb.x;
                        cur.y += acc[mi][ni][half * 2 + 1] + bb.y;
                        *p = cur;
                    }
                } else {
#pragma unroll
                    for (int ni = 0; ni < 8; ni++) {
                        int n = nbase + ni * 8;
                        float2 bb = *reinterpret_cast<const float2*>(b1 + n);
                        float2 o;
                        o.x = acc[mi][ni][half * 2 + 0] + bb.x;
                        o.y = acc[mi][ni][half * 2 + 1] + bb.y;
                        *reinterpret_cast<float2*>(A_buf + (size_t)row * 128 + n) = o;
                    }
                }
            }
        }
    }
}

// ---------------- gather: H[v] += sum_{j->v} A[j]  (warp per node) --------
__global__ void gather_kernel() {
    if (blockIdx.x == 0 && threadIdx.x == 0) { g_sum = 0.0; g_sumsq = 0.0; }
    int gw = (blockIdx.x * blockDim.x + threadIdx.x) >> 5;
    int lane = threadIdx.x & 31;
    if (gw >= Nn) return;
    int c = cnt_buf[gw];
    if (c > CAPB) c = CAPB;
    const int* bk = bucket_buf + (size_t)gw * CAPB;
    float4 acc = make_float4(0.f, 0.f, 0.f, 0.f);
    int e = 0;
    for (; e + 1 < c; e += 2) {
        int s0 = bk[e], s1 = bk[e + 1];
        float4 a0 = __ldg(reinterpret_cast<const float4*>(A_buf + (size_t)s0 * 128) + lane);
        float4 a1 = __ldg(reinterpret_cast<const float4*>(A_buf + (size_t)s1 * 128) + lane);
        acc.x += a0.x + a1.x; acc.y += a0.y + a1.y;
        acc.z += a0.z + a1.z; acc.w += a0.w + a1.w;
    }
    if (e < c) {
        int s0 = bk[e];
        float4 a0 = __ldg(reinterpret_cast<const float4*>(A_buf + (size_t)s0 * 128) + lane);
        acc.x += a0.x; acc.y += a0.y; acc.z += a0.z; acc.w += a0.w;
    }
    float4* hp = reinterpret_cast<float4*>(H_buf + (size_t)gw * 128) + lane;
    float4 h = *hp;
    h.x += acc.x; h.y += acc.y; h.z += acc.z; h.w += acc.w;
    *hp = h;
}

// ---------------- overflow edges (expected count: 0) ----------------------
__global__ void overflow_fix() {
    int m = ov_cnt;
    if (m > MAX_OV) m = MAX_OV;
    int lane = threadIdx.x & 31;
    int w = threadIdx.x >> 5;
    for (int e = w; e < m; e += 8) {
        int src = ov_src[e], dst = ov_dst[e];
        const float* ap = A_buf + (size_t)src * 128;
        float* hp = H_buf + (size_t)dst * 128;
        for (int k = lane; k < 128; k += 32) atomicAdd(&hp[k], ap[k]);
    }
}

// ---------------- global mean / sumsq (double accumulation) ---------------
__global__ void reduce_stats() {
    int idx = blockIdx.x * blockDim.x + threadIdx.x;
    int stride = gridDim.x * blockDim.x;
    double s = 0.0, ss = 0.0;
    const float4* h4 = reinterpret_cast<const float4*>(H_buf);
    for (int i = idx; i < NDTOT / 4; i += stride) {
        float4 v = h4[i];
        s  += (double)v.x + (double)v.y + (double)v.z + (double)v.w;
        ss += (double)v.x * v.x + (double)v.y * v.y +
              (double)v.z * v.z + (double)v.w * v.w;
    }
#pragma unroll
    for (int o = 16; o > 0; o >>= 1) {
        s  += __shfl_down_sync(0xffffffffu, s, o);
        ss += __shfl_down_sync(0xffffffffu, ss, o);
    }
    __shared__ double sh[2][8];
    int lane = threadIdx.x & 31, w = threadIdx.x >> 5;
    if (lane == 0) { sh[0][w] = s; sh[1][w] = ss; }
    __syncthreads();
    if (threadIdx.x == 0) {
        double ts = 0.0, tss = 0.0;
        for (int i = 0; i < (int)(blockDim.x >> 5); i++) { ts += sh[0][i]; tss += sh[1][i]; }
        atomicAdd(&g_sum, ts);
        atomicAdd(&g_sumsq, tss);
    }
}

// -- normalize + affine + leaky_relu + residual + bf16-split for next layer
__global__ void final_update(const float* __restrict__ lw, const float* __restrict__ lb,
                             const float* __restrict__ yin, float* __restrict__ yout,
                             int do_split) {
    double M = (double)NDTOT;
    double mean = g_sum / M;
    double var = g_sumsq / M - mean * mean;
    if (var < 0.0) var = 0.0;
    float inv = 1.0f / ((float)sqrt(var) + 1e-5f);
    float mf = (float)mean;

    int idx = blockIdx.x * blockDim.x + threadIdx.x;
    int stride = gridDim.x * blockDim.x;
    const float4* h4 = reinterpret_cast<const float4*>(H_buf);
    const float4* y4 = reinterpret_cast<const float4*>(yin);
    float4* o4 = reinterpret_cast<float4*>(yout);
    for (int i = idx; i < NDTOT / 4; i += stride) {
        int d = (i * 4) & 127;
        float4 w = *reinterpret_cast<const float4*>(lw + d);
        float4 b = *reinterpret_cast<const float4*>(lb + d);
        float4 h = h4[i];
        float4 y = y4[i];
        float t;
        float4 o;
        t = (h.x - mf) * inv; t = t * w.x + b.x; t = (t >= 0.f) ? t : 0.01f * t; o.x = y.x + t;
        t = (h.y - mf) * inv; t = t * w.y + b.y; t = (t >= 0.f) ? t : 0.01f * t; o.y = y.y + t;
        t = (h.z - mf) * inv; t = t * w.z + b.z; t = (t >= 0.f) ? t : 0.01f * t; o.z = y.z + t;
        t = (h.w - mf) * inv; t = t * w.w + b.w; t = (t >= 0.f) ? t : 0.01f * t; o.w = y.w + t;
        o4[i] = o;
        if (do_split) {
            __nv_bfloat16 hx = __float2bfloat16(o.x);
            __nv_bfloat16 hy = __float2bfloat16(o.y);
            __nv_bfloat16 hz = __float2bfloat16(o.z);
            __nv_bfloat16 hw = __float2bfloat16(o.w);
            __nv_bfloat16 lx = __float2bfloat16(o.x - __bfloat162float(hx));
            __nv_bfloat16 ly = __float2bfloat16(o.y - __bfloat162float(hy));
            __nv_bfloat16 lz = __float2bfloat16(o.z - __bfloat162float(hz));
            __nv_bfloat16 lww = __float2bfloat16(o.w - __bfloat162float(hw));
            *reinterpret_cast<__nv_bfloat162*>(Yh_buf + 4 * i)     = __halves2bfloat162(hx, hy);
            *reinterpret_cast<__nv_bfloat162*>(Yh_buf + 4 * i + 2) = __halves2bfloat162(hz, hw);
            *reinterpret_cast<__nv_bfloat162*>(Yl_buf + 4 * i)     = __halves2bfloat162(lx, ly);
            *reinterpret_cast<__nv_bfloat162*>(Yl_buf + 4 * i + 2) = __halves2bfloat162(lz, lww);
        }
    }
}

// ---------------------------------------------------------------------------
extern "C" void kernel_launch(void* const* d_in, const int* in_sizes, int n_in,
                              void* d_out, int out_size) {
    const float* y0 = (const float*)d_in[0];
    const int*   ei = (const int*)d_in[1];
    const float* W1 = (const float*)d_in[2];
    const float* b1 = (const float*)d_in[3];
    const float* W2 = (const float*)d_in[4];
    const float* W3 = (const float*)d_in[5];
    const float* b3 = (const float*)d_in[6];
    const float* lw = (const float*)d_in[7];
    const float* lb = (const float*)d_in[8];
    float* yout = (float*)d_out;

    (void)in_sizes; (void)n_in; (void)out_size;

    cudaFuncSetAttribute(gemm_fused, cudaFuncAttributeMaxDynamicSharedMemorySize, G_SMEM);

    init_kernel<<<(Nn + 255) / 256, 256>>>(ei);
    build_csr<<<(Ee + 255) / 256, 256>>>(ei);
    split_weights<<<(Ll * 3 * 16384 + 255) / 256, 256>>>(W1, W2, W3);
    split_y<<<(NDTOT / 2 + 255) / 256, 256>>>(y0);

    const int gemm_blocks = (Nn + 127) / 128;   // 782
    for (int l = 0; l < Ll; l++) {
        const float* yin = (l == 0) ? y0 : yout;
        gemm_fused<<<gemm_blocks, 256, G_SMEM>>>(l, b1 + (size_t)l * Dd, b3 + (size_t)l * Dd);
        gather_kernel<<<(Nn * 32 + 255) / 256, 256>>>();
        overflow_fix<<<1, 256>>>();
        reduce_stats<<<1024, 256>>>();
        final_update<<<1024, 256>>>(lw + (size_t)l * Dd, lb + (size_t)l * Dd, yin, yout,
                                    (l + 1 < Ll) ? 1 : 0);
    }
}

// round 5
// speedup vs baseline: 1.8810x; 1.0666x over previous
#include <cuda_runtime.h>
#include <cuda_bf16.h>
#include <math.h>
#include <stdint.h>

#define Nn 100000
#define Ee 1600000
#define Dd 128
#define Ll 3
#define CAPB 96
#define MAX_OV 8192
#define NDTOT (Nn * Dd)

// ---------------- device scratch ----------------
static __device__ float A_buf[NDTOT];
static __device__ float H_buf[NDTOT];
static __device__ int   cnt_buf[Nn];
static __device__ int   bucket_buf[Nn * CAPB];
static __device__ int   ov_src[MAX_OV];
static __device__ int   ov_dst[MAX_OV];
static __device__ int   ov_cnt;
static __device__ int   g_is64;
static __device__ double g_sum, g_sumsq;
static __device__ __nv_bfloat16 Yh_buf[NDTOT];
static __device__ __nv_bfloat16 Yl_buf[NDTOT];
// per layer 6 tiles of [n][k] bf16: W2h,W2l,W3h,W3l,W1h,W1l
static __device__ __nv_bfloat16 Wsp_buf[Ll * 6 * 128 * 128];

__device__ __forceinline__ uint32_t s2u(const void* p) {
    return (uint32_t)__cvta_generic_to_shared(p);
}

// ---------------- init ----------------
__global__ void init_kernel(const int* __restrict__ ei) {
    int i = blockIdx.x * blockDim.x + threadIdx.x;
    if (i < Nn) cnt_buf[i] = 0;
    if (i == 0) {
        ov_cnt = 0;
        int all0 = 1;
        for (int k = 0; k < 128; k++) {
            if (ei[2 * k + 1] != 0) { all0 = 0; break; }
        }
        g_is64 = all0;
    }
}

__device__ __forceinline__ int fetch_idx(const int* __restrict__ ei, int pos, int is64) {
    return is64 ? ei[2 * pos] : ei[pos];
}

__global__ void build_csr(const int* __restrict__ ei) {
    int e = blockIdx.x * blockDim.x + threadIdx.x;
    if (e >= Ee) return;
    int is64 = g_is64;
    int src = fetch_idx(ei, e, is64);
    int dst = fetch_idx(ei, Ee + e, is64);
    int pos = atomicAdd(&cnt_buf[dst], 1);
    if (pos < CAPB) {
        bucket_buf[(size_t)dst * CAPB + pos] = src;
    } else {
        int o = atomicAdd(&ov_cnt, 1);
        if (o < MAX_OV) { ov_src[o] = src; ov_dst[o] = dst; }
    }
}

// ----- prep: split Y and all weights to bf16 hi/lo (one launch) -----------
__global__ void prep_split(const float* __restrict__ Y,
                           const float* __restrict__ W1,
                           const float* __restrict__ W2,
                           const float* __restrict__ W3) {
    int idx = blockIdx.x * blockDim.x + threadIdx.x;
    if (idx < NDTOT / 2) {
        float2 v = *reinterpret_cast<const float2*>(Y + 2 * idx);
        __nv_bfloat16 hx = __float2bfloat16(v.x);
        __nv_bfloat16 hy = __float2bfloat16(v.y);
        __nv_bfloat16 lx = __float2bfloat16(v.x - __bfloat162float(hx));
        __nv_bfloat16 ly = __float2bfloat16(v.y - __bfloat162float(hy));
        *reinterpret_cast<__nv_bfloat162*>(Yh_buf + 2 * idx) = __halves2bfloat162(hx, hy);
        *reinterpret_cast<__nv_bfloat162*>(Yl_buf + 2 * idx) = __halves2bfloat162(lx, ly);
    }
    if (idx < Ll * 3 * 16384) {
        int lw = idx >> 14;
        int rem = idx & 16383;
        int k = rem >> 7, n = rem & 127;
        int l = lw / 3, w = lw % 3;
        const float* W = (w == 0) ? W2 : (w == 1) ? W3 : W1;
        float v = W[(size_t)l * 16384 + rem];
        __nv_bfloat16 h = __float2bfloat16(v);
        __nv_bfloat16 lo = __float2bfloat16(v - __bfloat162float(h));
        size_t base = ((size_t)l * 6 + (size_t)w * 2) * 16384;
        Wsp_buf[base + (size_t)n * 128 + k] = h;
        Wsp_buf[base + 16384 + (size_t)n * 128 + k] = lo;
    }
}

// ======================= HMMA helpers ==========================
__device__ __forceinline__ void mma_bf16(float* d, const uint32_t* a, const uint32_t* b) {
    asm volatile("mma.sync.aligned.m16n8k16.row.col.f32.bf16.bf16.f32 "
        "{%0,%1,%2,%3}, {%4,%5,%6,%7}, {%8,%9}, {%0,%1,%2,%3};"
        : "+f"(d[0]), "+f"(d[1]), "+f"(d[2]), "+f"(d[3])
        : "r"(a[0]), "r"(a[1]), "r"(a[2]), "r"(a[3]), "r"(b[0]), "r"(b[1]));
}
__device__ __forceinline__ void ldsm4(uint32_t* r, uint32_t addr) {
    asm volatile("ldmatrix.sync.aligned.m8n8.x4.shared.b16 {%0,%1,%2,%3}, [%4];"
        : "=r"(r[0]), "=r"(r[1]), "=r"(r[2]), "=r"(r[3]) : "r"(addr));
}
__device__ __forceinline__ void cpa16(uint32_t dst, const void* src, int srcsz) {
    asm volatile("cp.async.cg.shared.global [%0], [%1], 16, %2;"
                 :: "r"(dst), "l"(src), "r"(srcsz) : "memory");
}
#define CPA_COMMIT() asm volatile("cp.async.commit_group;" ::: "memory")
#define CPA_WAIT(n)  asm volatile("cp.async.wait_group %0;" :: "n"(n) : "memory")

#define TSTRIDE 272u
#define TILE_BYTES (128u * TSTRIDE)
#define T_OFF(i) ((uint32_t)(i) * TILE_BYTES)
#define G_SMEM (6u * TILE_BYTES)       // 208896

#define NTHR 512

__device__ __forceinline__ void copy_w_tile(uint32_t sb, uint32_t off,
                                            const __nv_bfloat16* __restrict__ g, int tid) {
#pragma unroll
    for (int i = tid; i < 2048; i += NTHR) {
        int n = i >> 4, c = i & 15;
        cpa16(sb + off + (uint32_t)n * TSTRIDE + (uint32_t)c * 16u,
              g + (size_t)n * 128 + c * 8, 16);
    }
}

// ===== fused GEMM (512 thr): A = Y@W1+b1 ; H = Y@W3+b3 - deg*(Y@W2) =======
// smem tiles: 0=Yh 1=Yl 2=Wa_h 3=Wa_l 4=Wb_h 5=Wb_l
__global__ void __launch_bounds__(NTHR) gemm_fused(int layer,
                                                   const float* __restrict__ b1,
                                                   const float* __restrict__ b3) {
    extern __shared__ char smem[];
    uint32_t sb = s2u(smem);
    int tid = threadIdx.x, lane = tid & 31, wid = tid >> 5;
    int warp_m = wid & 7, warp_n = wid >> 3;      // 8 x 2 warps, tile 16x64
    int base = blockIdx.x * 128;

    if (blockIdx.x == 0 && tid == 0) { g_sum = 0.0; g_sumsq = 0.0; }

    const __nv_bfloat16* wb = Wsp_buf + (size_t)layer * 6 * 16384;

    // group0: Y tiles + W1 (tiles 2,3)
    for (int t = 0; t < 2; t++) {
        const __nv_bfloat16* src = t ? Yl_buf : Yh_buf;
        uint32_t off = T_OFF(t);
#pragma unroll
        for (int i = tid; i < 2048; i += NTHR) {
            int n = i >> 4, c = i & 15;
            int row = base + n;
            int ok = (row < Nn);
            cpa16(sb + off + (uint32_t)n * TSTRIDE + (uint32_t)c * 16u,
                  src + (ok ? ((size_t)row * 128 + c * 8) : 0), ok ? 16 : 0);
        }
    }
    copy_w_tile(sb, T_OFF(2), wb + 4 * 16384, tid);   // W1h
    copy_w_tile(sb, T_OFF(3), wb + 5 * 16384, tid);   // W1l
    CPA_COMMIT();
    // group1: W2 (tiles 4,5)
    copy_w_tile(sb, T_OFF(4), wb + 0 * 16384, tid);   // W2h
    copy_w_tile(sb, T_OFF(5), wb + 1 * 16384, tid);   // W2l
    CPA_COMMIT();

    // ldmatrix address components (same mapping as validated round-4 kernel)
    uint32_t a_row = (uint32_t)(lane & 15);
    uint32_t a_hi  = (uint32_t)(lane >> 4) * 16u;
    uint32_t b_row = (uint32_t)((lane & 7) + ((lane >> 4) << 3));
    uint32_t b_hi  = (uint32_t)((lane >> 3) & 1) * 16u;
    int m_lane = lane >> 2;
    int nbase = warp_n * 64 + (lane & 3) * 2;
    uint32_t a_off_base = ((uint32_t)(warp_m * 16) + a_row) * TSTRIDE + a_hi;

    CPA_WAIT(1);            // Y + W1 resident
    __syncthreads();

    // ---------------- phase A: acc1 = Y@W1 ----------------
    float acc1[8][4];
#pragma unroll
    for (int ni = 0; ni < 8; ni++)
#pragma unroll
        for (int j = 0; j < 4; j++) acc1[ni][j] = 0.f;

#pragma unroll
    for (int k0 = 0; k0 < 8; k0++) {
        uint32_t kb = (uint32_t)k0 * 32u;
        uint32_t ah[4], al[4];
        ldsm4(ah, sb + T_OFF(0) + a_off_base + kb);
        ldsm4(al, sb + T_OFF(1) + a_off_base + kb);
#pragma unroll
        for (int bg = 0; bg < 4; bg++) {
            uint32_t rown = (uint32_t)(warp_n * 64 + bg * 16) + b_row;
            uint32_t off = rown * TSTRIDE + kb + b_hi;
            uint32_t bh[4], bl[4];
            ldsm4(bh, sb + T_OFF(2) + off);
            ldsm4(bl, sb + T_OFF(3) + off);
#pragma unroll
            for (int sub = 0; sub < 2; sub++) {
                int ni = bg * 2 + sub;
                mma_bf16(acc1[ni], ah, bh + 2 * sub);
                mma_bf16(acc1[ni], ah, bl + 2 * sub);
                mma_bf16(acc1[ni], al, bh + 2 * sub);
            }
        }
    }

    __syncthreads();                                   // done reading tiles 2,3
    copy_w_tile(sb, T_OFF(2), wb + 2 * 16384, tid);    // W3h
    copy_w_tile(sb, T_OFF(3), wb + 3 * 16384, tid);    // W3l
    CPA_COMMIT();

    // epilogue A (overlaps W3 cp.async)
    {
        int r0 = base + warp_m * 16 + m_lane;
#pragma unroll
        for (int half = 0; half < 2; half++) {
            int row = r0 + half * 8;
            if (row < Nn) {
#pragma unroll
                for (int ni = 0; ni < 8; ni++) {
                    int n = nbase + ni * 8;
                    float2 bb = *reinterpret_cast<const float2*>(b1 + n);
                    float2 o;
                    o.x = acc1[ni][half * 2 + 0] + bb.x;
                    o.y = acc1[ni][half * 2 + 1] + bb.y;
                    *reinterpret_cast<float2*>(A_buf + (size_t)row * 128 + n) = o;
                }
            }
        }
    }

    CPA_WAIT(0);           // W2 + W3 resident
    __syncthreads();

    // ---------------- phase B: acc2 = Y@W2 ; acc3 = Y@W3 ----------------
    float acc2[8][4], acc3[8][4];
#pragma unroll
    for (int ni = 0; ni < 8; ni++)
#pragma unroll
        for (int j = 0; j < 4; j++) { acc2[ni][j] = 0.f; acc3[ni][j] = 0.f; }

#pragma unroll
    for (int k0 = 0; k0 < 8; k0++) {
        uint32_t kb = (uint32_t)k0 * 32u;
        uint32_t ah[4], al[4];
        ldsm4(ah, sb + T_OFF(0) + a_off_base + kb);
        ldsm4(al, sb + T_OFF(1) + a_off_base + kb);
#pragma unroll
        for (int bg = 0; bg < 4; bg++) {
            uint32_t rown = (uint32_t)(warp_n * 64 + bg * 16) + b_row;
            uint32_t off = rown * TSTRIDE + kb + b_hi;
            uint32_t b2h[4], b2l[4], b3h[4], b3l[4];
            ldsm4(b2h, sb + T_OFF(4) + off);
            ldsm4(b2l, sb + T_OFF(5) + off);
            ldsm4(b3h, sb + T_OFF(2) + off);
            ldsm4(b3l, sb + T_OFF(3) + off);
#pragma unroll
            for (int sub = 0; sub < 2; sub++) {
                int ni = bg * 2 + sub;
                mma_bf16(acc2[ni], ah, b2h + 2 * sub);
                mma_bf16(acc3[ni], ah, b3h + 2 * sub);
                mma_bf16(acc2[ni], ah, b2l + 2 * sub);
                mma_bf16(acc3[ni], ah, b3l + 2 * sub);
                mma_bf16(acc2[ni], al, b2h + 2 * sub);
                mma_bf16(acc3[ni], al, b3h + 2 * sub);
            }
        }
    }

    // epilogue B: H = acc3 + b3 - deg*acc2
    {
        int r0 = base + warp_m * 16 + m_lane;
#pragma unroll
        for (int half = 0; half < 2; half++) {
            int row = r0 + half * 8;
            if (row < Nn) {
                float dg = (float)cnt_buf[row];
#pragma unroll
                for (int ni = 0; ni < 8; ni++) {
                    int n = nbase + ni * 8;
                    float2 bb = *reinterpret_cast<const float2*>(b3 + n);
                    float2 o;
                    o.x = acc3[ni][half * 2 + 0] + bb.x - dg * acc2[ni][half * 2 + 0];
                    o.y = acc3[ni][half * 2 + 1] + bb.y - dg * acc2[ni][half * 2 + 1];
                    *reinterpret_cast<float2*>(H_buf + (size_t)row * 128 + n) = o;
                }
            }
        }
    }
}

// ---------------- overflow edges (expected 0) -----------------------------
__global__ void overflow_fix() {
    int m = ov_cnt;
    if (m > MAX_OV) m = MAX_OV;
    int lane = threadIdx.x & 31;
    int w = threadIdx.x >> 5;
    for (int e = w; e < m; e += 8) {
        int src = ov_src[e], dst = ov_dst[e];
        const float* ap = A_buf + (size_t)src * 128;
        float* hp = H_buf + (size_t)dst * 128;
        for (int k = lane; k < 32; k += 32) {}
        for (int k = lane; k < 128; k += 32) atomicAdd(&hp[k], ap[k]);
    }
}

// ------- gather: H[v] += sum A[j]; fused global sum/sumsq stats -----------
__global__ void gather_kernel() {
    int tid = threadIdx.x;
    int gw = (blockIdx.x * 256 + tid) >> 5;          // exact: 12500*8 = 100000
    int lane = tid & 31;
    int c = cnt_buf[gw];
    if (c > CAPB) c = CAPB;
    const int* bk = bucket_buf + (size_t)gw * CAPB;
    float4 acc = make_float4(0.f, 0.f, 0.f, 0.f);
    int e = 0;
    for (; e + 1 < c; e += 2) {
        int s0 = bk[e], s1 = bk[e + 1];
        float4 a0 = __ldg(reinterpret_cast<const float4*>(A_buf + (size_t)s0 * 128) + lane);
        float4 a1 = __ldg(reinterpret_cast<const float4*>(A_buf + (size_t)s1 * 128) + lane);
        acc.x += a0.x + a1.x; acc.y += a0.y + a1.y;
        acc.z += a0.z + a1.z; acc.w += a0.w + a1.w;
    }
    if (e < c) {
        int s0 = bk[e];
        float4 a0 = __ldg(reinterpret_cast<const float4*>(A_buf + (size_t)s0 * 128) + lane);
        acc.x += a0.x; acc.y += a0.y; acc.z += a0.z; acc.w += a0.w;
    }
    float4* hp = reinterpret_cast<float4*>(H_buf + (size_t)gw * 128) + lane;
    float4 h = *hp;
    h.x += acc.x; h.y += acc.y; h.z += acc.z; h.w += acc.w;
    *hp = h;

    // fused stats on final H values (this warp owns the full row)
    double s  = (double)h.x + (double)h.y + (double)h.z + (double)h.w;
    double ss = (double)h.x * h.x + (double)h.y * h.y +
                (double)h.z * h.z + (double)h.w * h.w;
#pragma unroll
    for (int o = 16; o > 0; o >>= 1) {
        s  += __shfl_down_sync(0xffffffffu, s, o);
        ss += __shfl_down_sync(0xffffffffu, ss, o);
    }
    __shared__ double sh[2][8];
    int w = tid >> 5;
    if (lane == 0) { sh[0][w] = s; sh[1][w] = ss; }
    __syncthreads();
    if (tid == 0) {
        double ts = 0.0, tss = 0.0;
#pragma unroll
        for (int i = 0; i < 8; i++) { ts += sh[0][i]; tss += sh[1][i]; }
        atomicAdd(&g_sum, ts);
        atomicAdd(&g_sumsq, tss);
    }
}

// -- normalize + affine + leaky_relu + residual + bf16-split for next layer
__global__ void final_update(const float* __restrict__ lw, const float* __restrict__ lb,
                             const float* __restrict__ yin, float* __restrict__ yout,
                             int do_split) {
    double M = (double)NDTOT;
    double mean = g_sum / M;
    double var = g_sumsq / M - mean * mean;
    if (var < 0.0) var = 0.0;
    float inv = 1.0f / ((float)sqrt(var) + 1e-5f);
    float mf = (float)mean;

    int idx = blockIdx.x * blockDim.x + threadIdx.x;
    int stride = gridDim.x * blockDim.x;
    const float4* h4 = reinterpret_cast<const float4*>(H_buf);
    const float4* y4 = reinterpret_cast<const float4*>(yin);
    float4* o4 = reinterpret_cast<float4*>(yout);
    for (int i = idx; i < NDTOT / 4; i += stride) {
        int d = (i * 4) & 127;
        float4 w = *reinterpret_cast<const float4*>(lw + d);
        float4 b = *reinterpret_cast<const float4*>(lb + d);
        float4 h = h4[i];
        float4 y = y4[i];
        float t;
        float4 o;
        t = (h.x - mf) * inv; t = t * w.x + b.x; t = (t >= 0.f) ? t : 0.01f * t; o.x = y.x + t;
        t = (h.y - mf) * inv; t = t * w.y + b.y; t = (t >= 0.f) ? t : 0.01f * t; o.y = y.y + t;
        t = (h.z - mf) * inv; t = t * w.z + b.z; t = (t >= 0.f) ? t : 0.01f * t; o.z = y.z + t;
        t = (h.w - mf) * inv; t = t * w.w + b.w; t = (t >= 0.f) ? t : 0.01f * t; o.w = y.w + t;
        o4[i] = o;
        if (do_split) {
            __nv_bfloat16 hx = __float2bfloat16(o.x);
            __nv_bfloat16 hy = __float2bfloat16(o.y);
            __nv_bfloat16 hz = __float2bfloat16(o.z);
            __nv_bfloat16 hw = __float2bfloat16(o.w);
            __nv_bfloat16 lx = __float2bfloat16(o.x - __bfloat162float(hx));
            __nv_bfloat16 ly = __float2bfloat16(o.y - __bfloat162float(hy));
            __nv_bfloat16 lz = __float2bfloat16(o.z - __bfloat162float(hz));
            __nv_bfloat16 lww = __float2bfloat16(o.w - __bfloat162float(hw));
            *reinterpret_cast<__nv_bfloat162*>(Yh_buf + 4 * i)     = __halves2bfloat162(hx, hy);
            *reinterpret_cast<__nv_bfloat162*>(Yh_buf + 4 * i + 2) = __halves2bfloat162(hz, hw);
            *reinterpret_cast<__nv_bfloat162*>(Yl_buf + 4 * i)     = __halves2bfloat162(lx, ly);
            *reinterpret_cast<__nv_bfloat162*>(Yl_buf + 4 * i + 2) = __halves2bfloat162(lz, lww);
        }
    }
}

// ---------------------------------------------------------------------------
extern "C" void kernel_launch(void* const* d_in, const int* in_sizes, int n_in,
                              void* d_out, int out_size) {
    const float* y0 = (const float*)d_in[0];
    const int*   ei = (const int*)d_in[1];
    const float* W1 = (const float*)d_in[2];
    const float* b1 = (const float*)d_in[3];
    const float* W2 = (const float*)d_in[4];
    const float* W3 = (const float*)d_in[5];
    const float* b3 = (const float*)d_in[6];
    const float* lw = (const float*)d_in[7];
    const float* lb = (const float*)d_in[8];
    float* yout = (float*)d_out;

    (void)in_sizes; (void)n_in; (void)out_size;

    cudaFuncSetAttribute(gemm_fused, cudaFuncAttributeMaxDynamicSharedMemorySize, G_SMEM);

    init_kernel<<<(Nn + 255) / 256, 256>>>(ei);                       // #1
    build_csr<<<(Ee + 255) / 256, 256>>>(ei);                         // #2
    prep_split<<<(NDTOT / 2 + 255) / 256, 256>>>(y0, W1, W2, W3);     // #3

    const int gemm_blocks = (Nn + 127) / 128;   // 782
    for (int l = 0; l < Ll; l++) {
        const float* yin = (l == 0) ? y0 : yout;
        gemm_fused<<<gemm_blocks, NTHR, G_SMEM>>>(l, b1 + (size_t)l * Dd,
                                                  b3 + (size_t)l * Dd);   // #4 = profiled
        overflow_fix<<<1, 256>>>();
        gather_kernel<<<(Nn + 7) / 8, 256>>>();
        final_update<<<1024, 256>>>(lw + (size_t)l * Dd, lb + (size_t)l * Dd, yin, yout,
                                    (l + 1 < Ll) ? 1 : 0);
    }
}